// round 1
// baseline (speedup 1.0000x reference)
#include <cuda_runtime.h>
#include <math.h>

#define H_ 256
#define W_ 256
#define CIN_ 128
#define B_ 2
#define K_ 4
#define HWSZ (H_ * W_)

// ---------------- scratch (device globals; no allocation allowed) ----------------
__device__ float g_t1[B_ * CIN_ * HWSZ];    // gelu(conv3x3(query, ow1))
__device__ float g_off[B_ * 2 * K_ * HWSZ]; // offsets
__device__ float g_w1[B_ * 32 * HWSZ];      // gelu(conv3x3(query, ww1))
__device__ float g_agg[B_ * CIN_ * HWSZ];   // sampled+weighted aggregate

__device__ __forceinline__ float gelu_f(float x) {
    return 0.5f * x * (1.0f + erff(x * 0.70710678118654752440f));
}

// ---------------- generic 3x3 conv, Cin=128, pad=1, optional GELU ----------------
// Tile: 32 wide x 4 high = 128 pixels, COUT_TILE outputs. 256 threads.
// Thread: 4 pixels (x strided by 8) x NCO couts. cin chunks of 8.
template <int COUT_TILE, int NCO, bool DO_GELU>
__global__ __launch_bounds__(256) void conv3x3_kernel(
    const float* __restrict__ in, const float* __restrict__ wt,
    const float* __restrict__ bias, float* __restrict__ out, int Cout)
{
    constexpr int TW = 32, TH = 4, CINC = 8;
    constexpr int SW = 40;  // smem row stride; 40 % 32 == 8 -> conflict-free LDS
    __shared__ float s_in[CINC * (TH + 2) * SW];
    __shared__ float s_w[COUT_TILE * CINC * 9];

    const int tx = blockIdx.x & 7;          // W_/TW = 8
    const int ty = blockIdx.x >> 3;         // H_/TH = 64
    const int x0 = tx * TW, y0 = ty * TH;
    const int b = blockIdx.z;
    const int coB = blockIdx.y * COUT_TILE;
    const int tid = threadIdx.x;
    const int pg = tid & 31;
    const int cog = tid >> 5;               // 8 cout groups
    const int gxg = pg & 7;
    const int py = pg >> 3;
    const int co_base = cog * NCO;

    float acc[4][NCO];
#pragma unroll
    for (int j = 0; j < 4; j++)
#pragma unroll
        for (int c = 0; c < NCO; c++) acc[j][c] = 0.f;

    const float* inb = in + (size_t)b * CIN_ * HWSZ;

    for (int ci0 = 0; ci0 < CIN_; ci0 += CINC) {
        // load input tile (with zero padding)
        for (int idx = tid; idx < CINC * (TH + 2) * (TW + 2); idx += 256) {
            int c = idx / ((TH + 2) * (TW + 2));
            int rem = idx % ((TH + 2) * (TW + 2));
            int r = rem / (TW + 2), col = rem % (TW + 2);
            int iy = y0 + r - 1, ix = x0 + col - 1;
            float v = 0.f;
            if (iy >= 0 && iy < H_ && ix >= 0 && ix < W_)
                v = inb[(size_t)(ci0 + c) * HWSZ + iy * W_ + ix];
            s_in[(c * (TH + 2) + r) * SW + col] = v;
        }
        // load weight chunk: [COUT_TILE][CINC][9]
        for (int idx = tid; idx < COUT_TILE * CINC * 9; idx += 256) {
            int co = idx / (CINC * 9);
            int rem = idx % (CINC * 9);
            s_w[idx] = wt[(size_t)(coB + co) * CIN_ * 9 + ci0 * 9 + rem];
        }
        __syncthreads();

#pragma unroll 2
        for (int cc = 0; cc < CINC; ++cc) {
            const float* si = &s_in[(cc * (TH + 2) + py) * SW + gxg];
            const float* swp = &s_w[co_base * (CINC * 9) + cc * 9];
#pragma unroll
            for (int ky = 0; ky < 3; ++ky) {
                float iv[3][4];
#pragma unroll
                for (int kx = 0; kx < 3; kx++)
#pragma unroll
                    for (int j = 0; j < 4; j++)
                        iv[kx][j] = si[ky * SW + kx + 8 * j];
#pragma unroll
                for (int kx = 0; kx < 3; kx++) {
#pragma unroll
                    for (int c = 0; c < NCO; c++) {
                        float wv = swp[c * (CINC * 9) + ky * 3 + kx];
#pragma unroll
                        for (int j = 0; j < 4; j++)
                            acc[j][c] = fmaf(iv[kx][j], wv, acc[j][c]);
                    }
                }
            }
        }
        __syncthreads();
    }

    const int yy = y0 + py;
#pragma unroll
    for (int c = 0; c < NCO; c++) {
        int co = coB + co_base + c;
        float bv = bias[co];
#pragma unroll
        for (int j = 0; j < 4; j++) {
            float v = acc[j][c] + bv;
            if (DO_GELU) v = gelu_f(v);
            out[((size_t)b * Cout + co) * HWSZ + yy * W_ + x0 + gxg + 8 * j] = v;
        }
    }
}

// ---------------- sampler: wlog(1x1)+softmax, offsets->positions, K=4 bilinear ----
// One block: 64 consecutive x pixels of one row. 256 threads.
__global__ __launch_bounds__(256) void sampler_kernel(
    const float* __restrict__ key, const float* __restrict__ ww2,
    const float* __restrict__ wb2)
{
    __shared__ float s_ww2[K_ * 32];
    __shared__ float s_wb2[K_];
    __shared__ float s_logit[K_][64];
    __shared__ int   s_o[K_][4][64];
    __shared__ float s_wt[K_][4][64];

    const int b = blockIdx.z, y = blockIdx.y, x0 = blockIdx.x * 64;
    const int tid = threadIdx.x;
    if (tid < K_ * 32) s_ww2[tid] = ww2[tid];
    if (tid < K_) s_wb2[tid] = wb2[tid];
    __syncthreads();

    const int px = tid & 63;
    const int k = tid >> 6;
    const int x = x0 + px;

    // per-(pixel,k): offsets, logit, position
    const float* offb = g_off + (size_t)b * 2 * K_ * HWSZ + y * W_ + x;
    float ox = offb[(size_t)(2 * k) * HWSZ];
    float oy = offb[(size_t)(2 * k + 1) * HWSZ];

    const float* w1b = g_w1 + (size_t)b * 32 * HWSZ + y * W_ + x;
    float l = s_wb2[k];
#pragma unroll 8
    for (int c = 0; c < 32; c++) l = fmaf(s_ww2[k * 32 + c], w1b[(size_t)c * HWSZ], l);
    s_logit[k][px] = l;

    float bx = -1.f + 2.f * x * (1.f / (W_ - 1));
    float by = -1.f + 2.f * y * (1.f / (H_ - 1));
    float gxn = fminf(fmaxf(bx + ox * (2.f / W_), -1.f), 1.f);
    float gyn = fminf(fmaxf(by + oy * (2.f / H_), -1.f), 1.f);
    float pxf = (gxn + 1.f) * 0.5f * (W_ - 1);
    float pyf = (gyn + 1.f) * 0.5f * (H_ - 1);
    pxf = fminf(fmaxf(pxf, 0.f), (float)(W_ - 1));
    pyf = fminf(fmaxf(pyf, 0.f), (float)(H_ - 1));
    int ix0 = min((int)floorf(pxf), W_ - 1);
    int iy0 = min((int)floorf(pyf), H_ - 1);
    int ix1 = min(ix0 + 1, W_ - 1);
    int iy1 = min(iy0 + 1, H_ - 1);
    float fx = pxf - (float)ix0, fy = pyf - (float)iy0;
    __syncthreads();

    // softmax over K
    float m = fmaxf(fmaxf(s_logit[0][px], s_logit[1][px]),
                    fmaxf(s_logit[2][px], s_logit[3][px]));
    float se = 0.f;
#pragma unroll
    for (int q = 0; q < K_; q++) se += expf(s_logit[q][px] - m);
    float wk = expf(l - m) / se;

    s_o[k][0][px] = iy0 * W_ + ix0;
    s_o[k][1][px] = iy0 * W_ + ix1;
    s_o[k][2][px] = iy1 * W_ + ix0;
    s_o[k][3][px] = iy1 * W_ + ix1;
    s_wt[k][0][px] = wk * (1.f - fx) * (1.f - fy);
    s_wt[k][1][px] = wk * fx * (1.f - fy);
    s_wt[k][2][px] = wk * (1.f - fx) * fy;
    s_wt[k][3][px] = wk * fx * fy;
    __syncthreads();

    // hoist sample info to registers
    int o[K_][4]; float w[K_][4];
#pragma unroll
    for (int q = 0; q < K_; q++)
#pragma unroll
        for (int t = 0; t < 4; t++) { o[q][t] = s_o[q][t][px]; w[q][t] = s_wt[q][t][px]; }

    const int cq = tid >> 6;  // 4 channel lanes
    const float* keyb = key + (size_t)b * CIN_ * HWSZ;
    float* aggb = g_agg + (size_t)b * CIN_ * HWSZ + y * W_ + x;
    for (int it = 0; it < 32; ++it) {
        int c = it * 4 + cq;
        const float* kp = keyb + (size_t)c * HWSZ;
        float a = 0.f;
#pragma unroll
        for (int q = 0; q < K_; q++) {
            a = fmaf(kp[o[q][0]], w[q][0], a);
            a = fmaf(kp[o[q][1]], w[q][1], a);
            a = fmaf(kp[o[q][2]], w[q][2], a);
            a = fmaf(kp[o[q][3]], w[q][3], a);
        }
        aggb[(size_t)c * HWSZ] = a;
    }
}

// ---------------- fusion: conv1x1 -> gelu -> conv1x1, residual + 0.3 scale -------
// One block: 64 flattened pixels x all 128 channels, intermediate in smem.
__global__ __launch_bounds__(256) void fusion_kernel(
    const float* __restrict__ query,
    const float* __restrict__ fw1, const float* __restrict__ fb1,
    const float* __restrict__ fw2, const float* __restrict__ fb2,
    float* __restrict__ out)
{
    constexpr int PX = 64, SXS = 66;
    __shared__ float s_x[128 * SXS];   // intermediate f1 [128][64] padded
    __shared__ float s_in[16 * PX];
    __shared__ float s_w[128 * 16];

    const int b = blockIdx.y;
    const int p0 = blockIdx.x * PX;
    const int tid = threadIdx.x;
    const int pg = tid & 15;
    const int cog = tid >> 4;
    const int co0 = cog * 8;

    const float* aggb = g_agg + (size_t)b * 128 * HWSZ + p0;

    float acc[4][8];
#pragma unroll
    for (int j = 0; j < 4; j++)
#pragma unroll
        for (int c = 0; c < 8; c++) acc[j][c] = 0.f;

    // stage 1: f1 = gelu(fw1 @ agg + fb1)
    for (int ci0 = 0; ci0 < 128; ci0 += 16) {
        for (int idx = tid; idx < 16 * PX; idx += 256) {
            int c = idx >> 6, p = idx & 63;
            s_in[idx] = aggb[(size_t)(ci0 + c) * HWSZ + p];
        }
        for (int idx = tid; idx < 128 * 16; idx += 256) {
            int co = idx >> 4, ci = idx & 15;
            s_w[idx] = fw1[co * 128 + ci0 + ci];
        }
        __syncthreads();
#pragma unroll 4
        for (int ci = 0; ci < 16; ++ci) {
            float iv[4];
#pragma unroll
            for (int j = 0; j < 4; j++) iv[j] = s_in[ci * PX + pg + 16 * j];
#pragma unroll
            for (int c = 0; c < 8; c++) {
                float wv = s_w[(co0 + c) * 16 + ci];
#pragma unroll
                for (int j = 0; j < 4; j++) acc[j][c] = fmaf(iv[j], wv, acc[j][c]);
            }
        }
        __syncthreads();
    }
#pragma unroll
    for (int c = 0; c < 8; c++) {
        float bv = fb1[co0 + c];
#pragma unroll
        for (int j = 0; j < 4; j++)
            s_x[(co0 + c) * SXS + pg + 16 * j] = gelu_f(acc[j][c] + bv);
    }
    __syncthreads();

    // stage 2: out = query + 0.3 * (fw2 @ f1 + fb2)
    float acc2[4][8];
#pragma unroll
    for (int j = 0; j < 4; j++)
#pragma unroll
        for (int c = 0; c < 8; c++) acc2[j][c] = 0.f;

    for (int ci0 = 0; ci0 < 128; ci0 += 16) {
        for (int idx = tid; idx < 128 * 16; idx += 256) {
            int co = idx >> 4, ci = idx & 15;
            s_w[idx] = fw2[co * 128 + ci0 + ci];
        }
        __syncthreads();
#pragma unroll 4
        for (int ci = 0; ci < 16; ++ci) {
            float iv[4];
#pragma unroll
            for (int j = 0; j < 4; j++) iv[j] = s_x[(ci0 + ci) * SXS + pg + 16 * j];
#pragma unroll
            for (int c = 0; c < 8; c++) {
                float wv = s_w[(co0 + c) * 16 + ci];
#pragma unroll
                for (int j = 0; j < 4; j++) acc2[j][c] = fmaf(iv[j], wv, acc2[j][c]);
            }
        }
        __syncthreads();
    }

    const float* qb = query + (size_t)b * 128 * HWSZ + p0;
    float* ob = out + (size_t)b * 128 * HWSZ + p0;
#pragma unroll
    for (int c = 0; c < 8; c++) {
        float bv = fb2[co0 + c];
#pragma unroll
        for (int j = 0; j < 4; j++) {
            size_t idx = (size_t)(co0 + c) * HWSZ + pg + 16 * j;
            ob[idx] = qb[idx] + 0.3f * (acc2[j][c] + bv);
        }
    }
}

// ---------------- launch ----------------
extern "C" void kernel_launch(void* const* d_in, const int* in_sizes, int n_in,
                              void* d_out, int out_size)
{
    const float* query = (const float*)d_in[0];
    const float* key   = (const float*)d_in[1];
    const float* ow1 = (const float*)d_in[2];
    const float* ob1 = (const float*)d_in[3];
    const float* ow2 = (const float*)d_in[4];
    const float* ob2 = (const float*)d_in[5];
    const float* ww1 = (const float*)d_in[6];
    const float* wb1 = (const float*)d_in[7];
    const float* ww2 = (const float*)d_in[8];
    const float* wb2 = (const float*)d_in[9];
    const float* fw1 = (const float*)d_in[10];
    const float* fb1 = (const float*)d_in[11];
    const float* fw2 = (const float*)d_in[12];
    const float* fb2 = (const float*)d_in[13];
    float* out = (float*)d_out;

    float *t1p, *offp, *w1p;
    cudaGetSymbolAddress((void**)&t1p, g_t1);
    cudaGetSymbolAddress((void**)&offp, g_off);
    cudaGetSymbolAddress((void**)&w1p, g_w1);

    dim3 blk(256);
    // t1 = gelu(conv3x3(query, ow1))   Cout=128
    conv3x3_kernel<64, 8, true><<<dim3(512, 2, B_), blk>>>(query, ow1, ob1, t1p, 128);
    // offsets = conv3x3(t1, ow2)       Cout=8
    conv3x3_kernel<8, 1, false><<<dim3(512, 1, B_), blk>>>(t1p, ow2, ob2, offp, 8);
    // w1 = gelu(conv3x3(query, ww1))   Cout=32
    conv3x3_kernel<32, 4, true><<<dim3(512, 1, B_), blk>>>(query, ww1, wb1, w1p, 32);
    // sampler: wlog 1x1 + softmax + deformable bilinear gather -> g_agg
    sampler_kernel<<<dim3(W_ / 64, H_, B_), blk>>>(key, ww2, wb2);
    // fusion convs + residual
    fusion_kernel<<<dim3(HWSZ / 64, B_), blk>>>(query, fw1, fb1, fw2, fb2, out);
}